// round 11
// baseline (speedup 1.0000x reference)
#include <cuda_runtime.h>
#include <cuda_bf16.h>
#include <math.h>
#include <stdint.h>

static constexpr int Hh  = 96;
static constexpr int Ww  = 96;
static constexpr int HW  = 96 * 96;      // 9216
static constexpr int CIN = 64;
static constexpr int CO  = 128;
static constexpr int NB  = 8;

// Scratch (no cudaMalloc allowed).
__device__ float g_xt  [NB * HW * CIN];         // x transposed: [b][hw][c] fp32
__device__ __nv_bfloat16 g_xthi[NB * HW * CIN]; // bf16 hi split of x_t
__device__ __nv_bfloat16 g_xtlo[NB * HW * CIN]; // bf16 lo split of x_t
__device__ __nv_bfloat16 g_whi [18 * 4096];     // main weights [18 halves][8KB] hi
__device__ __nv_bfloat16 g_wlo [18 * 4096];     //                               lo
__device__ __nv_bfloat16 g_owhi[18 * 1024];     // off/mask weights [18 halves][2KB] hi
__device__ __nv_bfloat16 g_owlo[18 * 1024];     //                                  lo

// Half-chunk layout: [rows][32 k] bf16 = 64B/row; 16B chunk kc in 0..3 swizzled:
//   addr = r*64 + ((kc ^ ((r>>1)&3)) << 4)
__device__ __forceinline__ uint32_t rowadr(int r, int kc) {
    return (uint32_t)(r * 64 + (((kc) ^ ((r >> 1) & 3)) << 4));
}
__device__ __forceinline__ uint32_t smem_u32(const void* p) {
    uint32_t a;
    asm("{ .reg .u64 t; cvta.to.shared.u64 t, %1; cvt.u32.u64 %0, t; }" : "=r"(a) : "l"(p));
    return a;
}
__device__ __forceinline__ uint32_t pkbf(float a, float b) {
    __nv_bfloat162 t = __floats2bfloat162_rn(a, b);
    return *(uint32_t*)&t;
}
__device__ __forceinline__ void ldsm4(uint32_t* r, uint32_t a) {
    asm volatile("ldmatrix.sync.aligned.m8n8.x4.shared.b16 {%0,%1,%2,%3}, [%4];"
        : "=r"(r[0]), "=r"(r[1]), "=r"(r[2]), "=r"(r[3]) : "r"(a));
}
__device__ __forceinline__ void mma_bf16(float* d, const uint32_t* a,
                                         uint32_t b0, uint32_t b1) {
    asm volatile("mma.sync.aligned.m16n8k16.row.col.f32.bf16.bf16.f32 "
        "{%0,%1,%2,%3}, {%4,%5,%6,%7}, {%8,%9}, {%0,%1,%2,%3};"
        : "+f"(d[0]), "+f"(d[1]), "+f"(d[2]), "+f"(d[3])
        : "r"(a[0]), "r"(a[1]), "r"(a[2]), "r"(a[3]), "r"(b0), "r"(b1));
}
__device__ __forceinline__ void cpasync16(uint32_t dst, const void* src, int srcBytes) {
    asm volatile("cp.async.cg.shared.global [%0], [%1], 16, %2;"
        :: "r"(dst), "l"(src), "r"(srcBytes) : "memory");
}
__device__ __forceinline__ void cpasync_wait_all() {
    asm volatile("cp.async.wait_all;" ::: "memory");
}

// ---------------------------------------------------------------------------
// Kernel W: split main-conv weights into 18 pre-swizzled 32-k halves.
// ---------------------------------------------------------------------------
__global__ void k_wprep(const float* __restrict__ wgt) {
    int i = blockIdx.x * 256 + threadIdx.x;      // 128*576
    if (i >= 128 * 576) return;
    int o = i / 576, r = i % 576;
    int t = r / 64, c = r % 64;
    float v = wgt[o * 576 + c * 9 + t];
    __nv_bfloat16 h = __float2bfloat16(v);
    float lo = v - __bfloat162float(h);
    int hs = t * 2 + (c >> 5), cl = c & 31;
    int e = hs * 4096 + (int)(rowadr(o, cl >> 3) >> 1) + (cl & 7);
    g_whi[e] = h;
    g_wlo[e] = __float2bfloat16(lo);
}

// ---------------------------------------------------------------------------
// Kernel W2: split offset+mask weights [32 pad o][64 c] into 18 halves.
// ---------------------------------------------------------------------------
__global__ void k_wprep2(const float* __restrict__ ow, const float* __restrict__ mw) {
    int i = blockIdx.x * 256 + threadIdx.x;      // 9*32*64 = 18432
    if (i >= 18432) return;
    int t = i / 2048, r = i % 2048;
    int o = r / 64, c = r % 64;
    float v = 0.f;
    if (o < 18)      v = ow[o * 576 + c * 9 + t];
    else if (o < 27) v = mw[(o - 18) * 576 + c * 9 + t];
    __nv_bfloat16 h = __float2bfloat16(v);
    float lo = v - __bfloat162float(h);
    int hs = t * 2 + (c >> 5), cl = c & 31;
    int e = hs * 1024 + (int)(rowadr(o, cl >> 3) >> 1) + (cl & 7);
    g_owhi[e] = h;
    g_owlo[e] = __float2bfloat16(lo);
}

// ---------------------------------------------------------------------------
// Kernel X: transpose x[b][c][hw] -> g_xt[b][hw][c] (fp32) + bf16 hi/lo.
// ---------------------------------------------------------------------------
__global__ __launch_bounds__(256) void k_xt(const float* __restrict__ x) {
    __shared__ float t[32][33];
    const int b = blockIdx.z, c0 = blockIdx.y * 32, hw0 = blockIdx.x * 32;
    const int lx = threadIdx.x & 31, ly = threadIdx.x >> 5;
    const float* xb = x + (size_t)b * CIN * HW;
    #pragma unroll
    for (int j = ly; j < 32; j += 8)
        t[j][lx] = xb[(c0 + j) * HW + hw0 + lx];
    __syncthreads();
    float* xt = g_xt + (size_t)b * HW * CIN;
    __nv_bfloat16* xh = g_xthi + (size_t)b * HW * CIN;
    __nv_bfloat16* xl = g_xtlo + (size_t)b * HW * CIN;
    #pragma unroll
    for (int j = ly; j < 32; j += 8) {
        float v = t[lx][j];
        size_t idx = (size_t)(hw0 + j) * CIN + c0 + lx;
        xt[idx] = v;
        __nv_bfloat16 h = __float2bfloat16(v);
        xh[idx] = h;
        xl[idx] = __float2bfloat16(v - __bfloat162float(h));
    }
}

// ---------------------------------------------------------------------------
// Fused kernel, software-pipelined at 32-k half-chunk granularity.
// Iteration order: mma(slot s) FIRST, then stage(h+1 -> slot ~s), wait, barrier.
// smem: AHI 2x8K @0 | ALO 2x8K @16384 | BHI 2x8K @32768 | BLO 2x8K @49152 |
//       tapW @65536 | tapO @83968 | om @88576 | total 102400 (2 CTAs/SM)
// ---------------------------------------------------------------------------
static constexpr int SM_AHI  = 0;
static constexpr int SM_ALO  = 16384;
static constexpr int SM_BHI  = 32768;
static constexpr int SM_BLO  = 49152;
static constexpr int SM_TAPW = 65536;
static constexpr int SM_TAPO = 83968;
static constexpr int SM_OM   = 88576;
static constexpr int SM_TOTAL = 102400;

__global__ __launch_bounds__(256, 2) void k_main(
    const float* __restrict__ ob, const float* __restrict__ mb,
    const float* __restrict__ bias, float* __restrict__ out)
{
    extern __shared__ __align__(128) char smemc[];
    const uint32_t smem_base = smem_u32(smemc);
    const int tid  = threadIdx.x;
    const int wid  = tid >> 5, lane = tid & 31;
    const int b    = blockIdx.y;
    const int base = blockIdx.x * 128;

    const __nv_bfloat16* xh = g_xthi + (size_t)b * HW * CIN;
    const __nv_bfloat16* xl = g_xtlo + (size_t)b * HW * CIN;

    const int lr = lane & 15, gk = lane >> 4;

    // ================= phase 1: offset+mask conv (pipelined) =================
    {
        uint32_t aoffk[4], boffk[2];
        #pragma unroll
        for (int kc = 0; kc < 4; ++kc) aoffk[kc] = rowadr(lane, kc);
        #pragma unroll
        for (int ks = 0; ks < 2; ++ks) boffk[ks] = rowadr(wid * 16 + lr, ks * 2 + gk);

        // precomputed stage-B constants (2 items/thread)
        int sb_ho[2], sb_wo[2];
        uint32_t sb_adr[2];
        size_t sb_qb[2];
        #pragma unroll
        for (int it = 0; it < 2; ++it) {
            int i = tid + it * 256;
            int px = i >> 2, kc = i & 3;
            int p = base + px;
            sb_ho[it] = p / Ww;
            sb_wo[it] = p - sb_ho[it] * Ww;
            sb_adr[it] = rowadr(px, kc);
            sb_qb[it] = (size_t)(kc * 8);
        }

        float acc[2][2][4];
        #pragma unroll
        for (int mt = 0; mt < 2; ++mt)
            #pragma unroll
            for (int nt = 0; nt < 2; ++nt)
                #pragma unroll
                for (int j = 0; j < 4; ++j) acc[mt][nt][j] = 0.f;

        auto stageA1 = [&](int hs, int slot) {
            if (tid < 128)
                cpasync16(smem_base + SM_AHI + slot * 8192 + tid * 16,
                          (const char*)(g_owhi + hs * 1024) + tid * 16, 16);
            else {
                int t2 = tid - 128;
                cpasync16(smem_base + SM_ALO + slot * 8192 + t2 * 16,
                          (const char*)(g_owlo + hs * 1024) + t2 * 16, 16);
            }
        };
        auto stageB1 = [&](int hs, int slot) {
            const int ch = hs >> 1, co = (hs & 1) * 32;
            const int dy = ch / 3 - 1, dx = ch % 3 - 1;
            #pragma unroll
            for (int it = 0; it < 2; ++it) {
                int sy = sb_ho[it] + dy, sx = sb_wo[it] + dx;
                bool valid = (unsigned)sy < (unsigned)Hh && (unsigned)sx < (unsigned)Ww;
                int syc = min(max(sy, 0), Hh - 1), sxc = min(max(sx, 0), Ww - 1);
                size_t q = (size_t)(syc * Ww + sxc) * CIN + co + sb_qb[it];
                uint32_t adr = slot * 8192 + sb_adr[it];
                int nb = valid ? 16 : 0;
                cpasync16(smem_base + SM_BHI + adr, xh + q, nb);
                cpasync16(smem_base + SM_BLO + adr, xl + q, nb);
            }
        };

        stageA1(0, 0);
        stageB1(0, 0);
        cpasync_wait_all();
        __syncthreads();

        #pragma unroll 1
        for (int h = 0; h < 18; ++h) {
            const int s = h & 1;
            const uint32_t Ah = smem_base + SM_AHI + s * 8192;
            const uint32_t Al = smem_base + SM_ALO + s * 8192;
            const uint32_t Bh = smem_base + SM_BHI + s * 8192;
            const uint32_t Bl = smem_base + SM_BLO + s * 8192;
            #pragma unroll
            for (int ks = 0; ks < 2; ++ks) {
                uint32_t uh[4], vh[4], ul[4], vl[4], bh[4], bl[4];
                ldsm4(uh, Ah + aoffk[ks * 2]);
                ldsm4(vh, Ah + aoffk[ks * 2 + 1]);
                ldsm4(ul, Al + aoffk[ks * 2]);
                ldsm4(vl, Al + aoffk[ks * 2 + 1]);
                ldsm4(bh, Bh + boffk[ks]);
                ldsm4(bl, Bl + boffk[ks]);
                #pragma unroll
                for (int mt = 0; mt < 2; ++mt) {
                    uint32_t afh[4] = {uh[mt*2], uh[mt*2+1], vh[mt*2], vh[mt*2+1]};
                    uint32_t afl[4] = {ul[mt*2], ul[mt*2+1], vl[mt*2], vl[mt*2+1]};
                    float* d0 = acc[mt][0];
                    float* d1 = acc[mt][1];
                    mma_bf16(d0, afh, bh[0], bh[2]);
                    mma_bf16(d1, afh, bh[1], bh[3]);
                    mma_bf16(d0, afh, bl[0], bl[2]);
                    mma_bf16(d1, afh, bl[1], bl[3]);
                    mma_bf16(d0, afl, bh[0], bh[2]);
                    mma_bf16(d1, afl, bh[1], bh[3]);
                }
            }
            if (h < 17) { stageA1(h + 1, s ^ 1); stageB1(h + 1, s ^ 1); }
            cpasync_wait_all();
            __syncthreads();
        }

        // epilogue -> smem om[27][128]
        float* om = (float*)(smemc + SM_OM);
        const int row = lane >> 2, colp = (lane & 3) * 2;
        #pragma unroll
        for (int mt = 0; mt < 2; ++mt) {
            #pragma unroll
            for (int nt = 0; nt < 2; ++nt) {
                const float* d = acc[mt][nt];
                int p = wid * 16 + nt * 8 + colp;
                #pragma unroll
                for (int half = 0; half < 2; ++half) {
                    int o = mt * 16 + half * 8 + row;
                    float v0 = d[half * 2], v1 = d[half * 2 + 1];
                    if (o < 18) {
                        float bo = ob[o];
                        *(float2*)(om + o * 128 + p) = make_float2(v0 + bo, v1 + bo);
                    } else if (o < 27) {
                        float bo = mb[o - 18];
                        float s0 = 1.f / (1.f + __expf(-(v0 + bo)));
                        float s1 = 1.f / (1.f + __expf(-(v1 + bo)));
                        *(float2*)(om + o * 128 + p) = make_float2(s0, s1);
                    }
                }
            }
        }
    }
    __syncthreads();

    // ================= phase 2: tap table =================
    {
        const float* om = (const float*)(smemc + SM_OM);
        #pragma unroll 1
        for (int i = tid; i < 128 * 9; i += 256) {
            int pxl = i / 9, t = i % 9;
            int p = base + pxl;
            int ho = p / Ww, wo = p - ho * Ww;
            float dy = om[(2 * t) * 128 + pxl];
            float dx = om[(2 * t + 1) * 128 + pxl];
            float m  = om[(18 + t) * 128 + pxl];
            float fy = (float)(ho - 1 + t / 3) + dy;
            float fx = (float)(wo - 1 + t % 3) + dx;
            float y0f = floorf(fy), x0f = floorf(fx);
            int y0 = (int)y0f, x0 = (int)x0f;
            float ly = fy - y0f, lx = fx - x0f;
            float hy = 1.f - ly, hx = 1.f - lx;
            float rwA = 0.f, rwB = 0.f, cwA = 0.f, cwB = 0.f;
            if (y0 >= 0 && y0 <= Hh - 2)      { rwA = hy; rwB = ly; }
            else if (y0 == -1)                { rwA = ly; }
            else if (y0 == Hh - 1)            { rwB = hy; }
            if (x0 >= 0 && x0 <= Ww - 2)      { cwA = hx; cwB = lx; }
            else if (x0 == -1)                { cwA = lx; }
            else if (x0 == Ww - 1)            { cwB = hx; }
            rwA *= m; rwB *= m;
            int by = min(max(y0, 0), Hh - 2);
            int bx = min(max(x0, 0), Ww - 2);
            ((float4*)(smemc + SM_TAPW))[i] = make_float4(rwA, rwB, cwA, cwB);
            ((int*)(smemc + SM_TAPO))[i] = (by * Ww + bx) * CIN;
        }
    }
    __syncthreads();

    // ================= phase 3: deform GEMM (pipelined) =================
    const int warp_m = wid & 3, warp_n = wid >> 2;
    uint32_t aoffk[4], boff3[2][4];
    #pragma unroll
    for (int kc = 0; kc < 4; ++kc) aoffk[kc] = rowadr(warp_m * 32 + lane, kc);
    #pragma unroll
    for (int ks = 0; ks < 2; ++ks)
        #pragma unroll
        for (int nt = 0; nt < 4; ++nt)
            boff3[ks][nt] = rowadr(warp_n * 64 + nt * 16 + lr, ks * 2 + gk);

    // precomputed im2col constants (4 items/thread)
    int ic_px9[4], ic_qb[4];
    uint32_t ic_adr[4];
    #pragma unroll
    for (int it = 0; it < 4; ++it) {
        int i = tid + it * 256;
        int px = i >> 3, q = i & 7;
        ic_px9[it] = px * 9;
        ic_qb[it]  = q * 4;
        ic_adr[it] = rowadr(px, q >> 1) + (q & 1) * 8;
    }

    float acc[64];
    #pragma unroll
    for (int i = 0; i < 64; ++i) acc[i] = 0.f;

    const float* xtb = g_xt + (size_t)b * HW * CIN;

    auto stageA3 = [&](int hs, int slot) {
        #pragma unroll
        for (int j = 0; j < 2; ++j) {
            int i = tid + j * 256;   // 0..511 (16B chunks)
            cpasync16(smem_base + SM_AHI + slot * 8192 + i * 16,
                      (const char*)(g_whi + hs * 4096) + i * 16, 16);
            cpasync16(smem_base + SM_ALO + slot * 8192 + i * 16,
                      (const char*)(g_wlo + hs * 4096) + i * 16, 16);
        }
    };
    auto im2col3 = [&](int hs, int slot) {
        const int ch = hs >> 1, co = (hs & 1) * 32;
        #pragma unroll
        for (int it = 0; it < 4; ++it) {
            int ti = ic_px9[it] + ch;
            float4 w = ((const float4*)(smemc + SM_TAPW))[ti];
            int offA = ((const int*)(smemc + SM_TAPO))[ti];
            const float* pb = xtb + offA + co + ic_qb[it];
            float4 p00 = *(const float4*)(pb);
            float4 p01 = *(const float4*)(pb + CIN);
            float4 p10 = *(const float4*)(pb + Ww * CIN);
            float4 p11 = *(const float4*)(pb + Ww * CIN + CIN);
            float v0 = w.x * (w.z * p00.x + w.w * p01.x) + w.y * (w.z * p10.x + w.w * p11.x);
            float v1 = w.x * (w.z * p00.y + w.w * p01.y) + w.y * (w.z * p10.y + w.w * p11.y);
            float v2 = w.x * (w.z * p00.z + w.w * p01.z) + w.y * (w.z * p10.z + w.w * p11.z);
            float v3 = w.x * (w.z * p00.w + w.w * p01.w) + w.y * (w.z * p10.w + w.w * p11.w);
            __nv_bfloat16 h0 = __float2bfloat16(v0), h1 = __float2bfloat16(v1);
            __nv_bfloat16 h2 = __float2bfloat16(v2), h3 = __float2bfloat16(v3);
            uint2 hiv, lov;
            { __nv_bfloat162 a; a.x = h0; a.y = h1; hiv.x = *(uint32_t*)&a; }
            { __nv_bfloat162 c; c.x = h2; c.y = h3; hiv.y = *(uint32_t*)&c; }
            lov.x = pkbf(v0 - __bfloat162float(h0), v1 - __bfloat162float(h1));
            lov.y = pkbf(v2 - __bfloat162float(h2), v3 - __bfloat162float(h3));
            uint32_t adr = slot * 8192 + ic_adr[it];
            *(uint2*)(smemc + SM_BHI + adr) = hiv;
            *(uint2*)(smemc + SM_BLO + adr) = lov;
        }
    };

    stageA3(0, 0);
    im2col3(0, 0);
    cpasync_wait_all();
    __syncthreads();

    #pragma unroll 1
    for (int h = 0; h < 18; ++h) {
        const int s = h & 1;
        const uint32_t Ah = smem_base + SM_AHI + s * 8192;
        const uint32_t Al = smem_base + SM_ALO + s * 8192;
        const uint32_t Bh = smem_base + SM_BHI + s * 8192;
        const uint32_t Bl = smem_base + SM_BLO + s * 8192;
        #pragma unroll
        for (int ks = 0; ks < 2; ++ks) {
            uint32_t uh[4], vh[4], ul[4], vl[4];
            ldsm4(uh, Ah + aoffk[ks * 2]);
            ldsm4(vh, Ah + aoffk[ks * 2 + 1]);
            ldsm4(ul, Al + aoffk[ks * 2]);
            ldsm4(vl, Al + aoffk[ks * 2 + 1]);
            #pragma unroll
            for (int nt = 0; nt < 4; ++nt) {
                uint32_t bh[4], bl[4];
                ldsm4(bh, Bh + boff3[ks][nt]);
                ldsm4(bl, Bl + boff3[ks][nt]);
                #pragma unroll
                for (int mt = 0; mt < 2; ++mt) {
                    uint32_t afh[4] = {uh[mt*2], uh[mt*2+1], vh[mt*2], vh[mt*2+1]};
                    uint32_t afl[4] = {ul[mt*2], ul[mt*2+1], vl[mt*2], vl[mt*2+1]};
                    float* d0 = acc + (mt * 8 + nt * 2) * 4;
                    float* d1 = d0 + 4;
                    mma_bf16(d0, afh, bh[0], bh[2]);
                    mma_bf16(d1, afh, bh[1], bh[3]);
                    mma_bf16(d0, afh, bl[0], bl[2]);
                    mma_bf16(d1, afh, bl[1], bl[3]);
                    mma_bf16(d0, afl, bh[0], bh[2]);
                    mma_bf16(d1, afl, bh[1], bh[3]);
                }
            }
        }
        if (h < 17) { stageA3(h + 1, s ^ 1); im2col3(h + 1, s ^ 1); }
        cpasync_wait_all();
        __syncthreads();
    }

    const int row  = lane >> 2, colp = (lane & 3) * 2;
    float* outb = out + (size_t)b * CO * HW + base;
    #pragma unroll
    for (int mt = 0; mt < 2; ++mt) {
        int o0 = warp_m * 32 + mt * 16 + row;
        float b0 = bias[o0], b1 = bias[o0 + 8];
        #pragma unroll
        for (int n8 = 0; n8 < 8; ++n8) {
            const float* d = acc + (mt * 8 + n8) * 4;
            int pxo = warp_n * 64 + n8 * 8 + colp;
            *(float2*)(outb + (size_t)o0 * HW + pxo)       = make_float2(d[0] + b0, d[1] + b0);
            *(float2*)(outb + (size_t)(o0 + 8) * HW + pxo) = make_float2(d[2] + b1, d[3] + b1);
        }
    }
}

// ---------------------------------------------------------------------------
extern "C" void kernel_launch(void* const* d_in, const int* in_sizes, int n_in,
                              void* d_out, int out_size)
{
    const float* x   = (const float*)d_in[0];   // [8,64,96,96]
    const float* ow  = (const float*)d_in[1];   // [18,64,3,3]
    const float* ob  = (const float*)d_in[2];   // [18]
    const float* mw  = (const float*)d_in[3];   // [9,64,3,3]
    const float* mb  = (const float*)d_in[4];   // [9]
    const float* wgt = (const float*)d_in[5];   // [128,64,3,3]
    const float* bs  = (const float*)d_in[6];   // [128]
    float* out = (float*)d_out;                 // [8,128,96,96]

    cudaFuncSetAttribute(k_main, cudaFuncAttributeMaxDynamicSharedMemorySize, SM_TOTAL);

    k_wprep  <<<288, 256>>>(wgt);
    k_wprep2 <<<72, 256>>>(ow, mw);
    k_xt     <<<dim3(288, 2, 8), 256>>>(x);
    k_main   <<<dim3(72, 8), 256, SM_TOTAL>>>(ob, mb, bs, out);
}

// round 12
// speedup vs baseline: 1.4637x; 1.4637x over previous
#include <cuda_runtime.h>
#include <cuda_fp16.h>
#include <math.h>
#include <stdint.h>

static constexpr int Hh  = 96;
static constexpr int Ww  = 96;
static constexpr int HW  = 96 * 96;      // 9216
static constexpr int CIN = 64;
static constexpr int CO  = 128;
static constexpr int NB  = 8;

// Scratch (no cudaMalloc allowed).
__device__ float  g_xt [NB * HW * CIN];         // x transposed: [b][hw][c] fp32
__device__ __half g_xth[NB * HW * CIN];         // fp16 of x_t
__device__ __half g_whi [9 * 8192];             // main weights per-tap swizzled fp16 hi
__device__ __half g_wlo [9 * 8192];             //                               fp16 lo
__device__ __half g_owhi[9 * 2048];             // off/mask weights [32 pad][64] hi
__device__ __half g_owlo[9 * 2048];             //                               lo

__device__ __forceinline__ int swz(int off) { return off ^ ((off >> 3) & 0x70); }
__device__ __forceinline__ uint32_t smem_u32(const void* p) {
    uint32_t a;
    asm("{ .reg .u64 t; cvta.to.shared.u64 t, %1; cvt.u32.u64 %0, t; }" : "=r"(a) : "l"(p));
    return a;
}
__device__ __forceinline__ void ldsm4(uint32_t* r, uint32_t a) {
    asm volatile("ldmatrix.sync.aligned.m8n8.x4.shared.b16 {%0,%1,%2,%3}, [%4];"
        : "=r"(r[0]), "=r"(r[1]), "=r"(r[2]), "=r"(r[3]) : "r"(a));
}
__device__ __forceinline__ void mma_fp16(float* d, const uint32_t* a,
                                         uint32_t b0, uint32_t b1) {
    asm volatile("mma.sync.aligned.m16n8k16.row.col.f32.f16.f16.f32 "
        "{%0,%1,%2,%3}, {%4,%5,%6,%7}, {%8,%9}, {%0,%1,%2,%3};"
        : "+f"(d[0]), "+f"(d[1]), "+f"(d[2]), "+f"(d[3])
        : "r"(a[0]), "r"(a[1]), "r"(a[2]), "r"(a[3]), "r"(b0), "r"(b1));
}
__device__ __forceinline__ void cpasync16(uint32_t dst, const void* src, int srcBytes) {
    asm volatile("cp.async.cg.shared.global [%0], [%1], 16, %2;"
        :: "r"(dst), "l"(src), "r"(srcBytes) : "memory");
}
__device__ __forceinline__ void cpasync_wait_all() {
    asm volatile("cp.async.wait_all;" ::: "memory");
}

// ---------------------------------------------------------------------------
// Kernel W: split main-conv weights into fp16 hi/lo (tap-major k, SW128).
// ---------------------------------------------------------------------------
__global__ void k_wprep(const float* __restrict__ wgt) {
    int i = blockIdx.x * 256 + threadIdx.x;      // 128*576
    if (i >= 128 * 576) return;
    int o = i / 576, r = i % 576;
    int t = r / 64, c = r % 64;
    float v = wgt[o * 576 + c * 9 + t];
    __half h = __float2half_rn(v);
    float lo = v - __half2float(h);
    int sw = swz(o * 128 + c * 2) >> 1;
    g_whi[t * 8192 + sw] = h;
    g_wlo[t * 8192 + sw] = __float2half_rn(lo);
}

// ---------------------------------------------------------------------------
// Kernel W2: split offset+mask weights [32 pad o][64 c] per tap, fp16 hi/lo.
// ---------------------------------------------------------------------------
__global__ void k_wprep2(const float* __restrict__ ow, const float* __restrict__ mw) {
    int i = blockIdx.x * 256 + threadIdx.x;      // 9*32*64 = 18432
    if (i >= 18432) return;
    int t = i / 2048, r = i % 2048;
    int o = r / 64, c = r % 64;
    float v = 0.f;
    if (o < 18)      v = ow[o * 576 + c * 9 + t];
    else if (o < 27) v = mw[(o - 18) * 576 + c * 9 + t];
    __half h = __float2half_rn(v);
    float lo = v - __half2float(h);
    int sw = swz(o * 128 + c * 2) >> 1;
    g_owhi[t * 2048 + sw] = h;
    g_owlo[t * 2048 + sw] = __float2half_rn(lo);
}

// ---------------------------------------------------------------------------
// Kernel X: transpose x[b][c][hw] -> g_xt[b][hw][c] (fp32) + fp16.
// ---------------------------------------------------------------------------
__global__ __launch_bounds__(256) void k_xt(const float* __restrict__ x) {
    __shared__ float t[32][33];
    const int b = blockIdx.z, c0 = blockIdx.y * 32, hw0 = blockIdx.x * 32;
    const int lx = threadIdx.x & 31, ly = threadIdx.x >> 5;
    const float* xb = x + (size_t)b * CIN * HW;
    #pragma unroll
    for (int j = ly; j < 32; j += 8)
        t[j][lx] = xb[(c0 + j) * HW + hw0 + lx];
    __syncthreads();
    float* xt  = g_xt  + (size_t)b * HW * CIN;
    __half* xh = g_xth + (size_t)b * HW * CIN;
    #pragma unroll
    for (int j = ly; j < 32; j += 8) {
        float v = t[lx][j];
        size_t idx = (size_t)(hw0 + j) * CIN + c0 + lx;
        xt[idx] = v;
        xh[idx] = __float2half_rn(v);
    }
}

// ---------------------------------------------------------------------------
// Fused kernel (R7 structure): offset/mask conv (2-split fp16 mma) -> smem ->
// tap table -> deform GEMM (2-split fp16 mma). 9 chunks of 64-k each phase.
// smem: A_hi 0 (16K) | A_lo 16384 (16K) | B 32768 (16K) |
//       tapW 49152 (18432) | tapO 67584 (4608) | om 72192 (13824)
//       total 86016 -> 2 CTAs/SM
// ---------------------------------------------------------------------------
static constexpr int SM_AHI  = 0;
static constexpr int SM_ALO  = 16384;
static constexpr int SM_B    = 32768;
static constexpr int SM_TAPW = 49152;
static constexpr int SM_TAPO = 67584;
static constexpr int SM_OM   = 72192;
static constexpr int SM_TOTAL = 86016;

__global__ __launch_bounds__(256, 2) void k_main(
    const float* __restrict__ ob, const float* __restrict__ mb,
    const float* __restrict__ bias, float* __restrict__ out)
{
    extern __shared__ __align__(128) char smemc[];
    const uint32_t smem_base = smem_u32(smemc);
    const int tid  = threadIdx.x;
    const int wid  = tid >> 5, lane = tid & 31;
    const int b    = blockIdx.y;
    const int base = blockIdx.x * 128;

    const __half* xhp = g_xth + (size_t)b * HW * CIN;
    const int lr = lane & 15, gk = lane >> 4;

    // ================= phase 1: offset+mask conv =================
    {
        uint32_t aoffm[2][4], boff[4];
        #pragma unroll
        for (int mt = 0; mt < 2; ++mt) {
            int aRow = mt * 16 + lr;
            #pragma unroll
            for (int ks = 0; ks < 4; ++ks)
                aoffm[mt][ks] = aRow * 128 + (((2 * ks + gk) ^ (aRow & 7)) << 4);
        }
        {
            int bRow = wid * 16 + lr;
            #pragma unroll
            for (int ks = 0; ks < 4; ++ks)
                boff[ks] = bRow * 128 + (((2 * ks + gk) ^ (bRow & 7)) << 4);
        }

        float acc[2][2][4];
        #pragma unroll
        for (int mt = 0; mt < 2; ++mt)
            #pragma unroll
            for (int nt = 0; nt < 2; ++nt)
                #pragma unroll
                for (int j = 0; j < 4; ++j) acc[mt][nt][j] = 0.f;

        for (int ch = 0; ch < 9; ++ch) {
            __syncthreads();
            // stage A hi+lo via cp.async (4KB each)
            if (tid < 128) {
                cpasync16(smem_base + SM_AHI + tid * 32,      (const char*)(g_owhi + ch * 2048) + tid * 32,      16);
                cpasync16(smem_base + SM_AHI + tid * 32 + 16, (const char*)(g_owhi + ch * 2048) + tid * 32 + 16, 16);
            } else {
                int t2 = tid - 128;
                cpasync16(smem_base + SM_ALO + t2 * 32,      (const char*)(g_owlo + ch * 2048) + t2 * 32,      16);
                cpasync16(smem_base + SM_ALO + t2 * 32 + 16, (const char*)(g_owlo + ch * 2048) + t2 * 32 + 16, 16);
            }
            // stage B (fp16, hi only) via cp.async with zfill on borders
            {
                const int dy = ch / 3 - 1, dx = ch % 3 - 1;
                #pragma unroll
                for (int it = 0; it < 4; ++it) {
                    int i = tid + it * 256;         // 1024 items: 128px x 8 chunks
                    int pxl = i >> 3, ci = i & 7;
                    int p = base + pxl;
                    int ho = p / Ww, wo = p - ho * Ww;
                    int sy = ho + dy, sx = wo + dx;
                    bool valid = (unsigned)sy < (unsigned)Hh && (unsigned)sx < (unsigned)Ww;
                    int syc = min(max(sy, 0), Hh - 1), sxc = min(max(sx, 0), Ww - 1);
                    size_t q = (size_t)(syc * Ww + sxc) * CIN + ci * 8;
                    int sw = swz(pxl * 128 + ci * 16);
                    cpasync16(smem_base + SM_B + sw, xhp + q, valid ? 16 : 0);
                }
            }
            cpasync_wait_all();
            __syncthreads();

            const uint32_t Ahi = smem_base + SM_AHI, Alo = smem_base + SM_ALO;
            const uint32_t Bp  = smem_base + SM_B;
            #pragma unroll
            for (int ks = 0; ks < 4; ++ks) {
                uint32_t ah[2][4], al[2][4], bh[4];
                ldsm4(ah[0], Ahi + aoffm[0][ks]);
                ldsm4(ah[1], Ahi + aoffm[1][ks]);
                ldsm4(al[0], Alo + aoffm[0][ks]);
                ldsm4(al[1], Alo + aoffm[1][ks]);
                ldsm4(bh, Bp + boff[ks]);
                #pragma unroll
                for (int mt = 0; mt < 2; ++mt) {
                    float* d0 = acc[mt][0];
                    float* d1 = acc[mt][1];
                    mma_fp16(d0, ah[mt], bh[0], bh[2]);
                    mma_fp16(d1, ah[mt], bh[1], bh[3]);
                    mma_fp16(d0, al[mt], bh[0], bh[2]);
                    mma_fp16(d1, al[mt], bh[1], bh[3]);
                }
            }
        }
        __syncthreads();   // all ldsm/mma done before om write (aliases nothing, but order anyway)

        // epilogue -> smem om[27][128]
        float* om = (float*)(smemc + SM_OM);
        const int row = lane >> 2, colp = (lane & 3) * 2;
        #pragma unroll
        for (int mt = 0; mt < 2; ++mt) {
            #pragma unroll
            for (int nt = 0; nt < 2; ++nt) {
                const float* d = acc[mt][nt];
                int p = wid * 16 + nt * 8 + colp;
                #pragma unroll
                for (int half = 0; half < 2; ++half) {
                    int o = mt * 16 + half * 8 + row;
                    float v0 = d[half * 2], v1 = d[half * 2 + 1];
                    if (o < 18) {
                        float bo = ob[o];
                        *(float2*)(om + o * 128 + p) = make_float2(v0 + bo, v1 + bo);
                    } else if (o < 27) {
                        float bo = mb[o - 18];
                        float s0 = 1.f / (1.f + __expf(-(v0 + bo)));
                        float s1 = 1.f / (1.f + __expf(-(v1 + bo)));
                        *(float2*)(om + o * 128 + p) = make_float2(s0, s1);
                    }
                }
            }
        }
    }
    __syncthreads();

    // ================= phase 2: tap table =================
    {
        const float* om = (const float*)(smemc + SM_OM);
        for (int i = tid; i < 128 * 9; i += 256) {
            int pxl = i / 9, t = i % 9;
            int p = base + pxl;
            int ho = p / Ww, wo = p - ho * Ww;
            float dy = om[(2 * t) * 128 + pxl];
            float dx = om[(2 * t + 1) * 128 + pxl];
            float m  = om[(18 + t) * 128 + pxl];
            float fy = (float)(ho - 1 + t / 3) + dy;
            float fx = (float)(wo - 1 + t % 3) + dx;
            float y0f = floorf(fy), x0f = floorf(fx);
            int y0 = (int)y0f, x0 = (int)x0f;
            float ly = fy - y0f, lx = fx - x0f;
            float hy = 1.f - ly, hx = 1.f - lx;
            float rwA = 0.f, rwB = 0.f, cwA = 0.f, cwB = 0.f;
            if (y0 >= 0 && y0 <= Hh - 2)      { rwA = hy; rwB = ly; }
            else if (y0 == -1)                { rwA = ly; }
            else if (y0 == Hh - 1)            { rwB = hy; }
            if (x0 >= 0 && x0 <= Ww - 2)      { cwA = hx; cwB = lx; }
            else if (x0 == -1)                { cwA = lx; }
            else if (x0 == Ww - 1)            { cwB = hx; }
            rwA *= m; rwB *= m;
            int by = min(max(y0, 0), Hh - 2);
            int bx = min(max(x0, 0), Ww - 2);
            ((float4*)(smemc + SM_TAPW))[i] = make_float4(rwA, rwB, cwA, cwB);
            ((int*)(smemc + SM_TAPO))[i] = (by * Ww + bx) * CIN;
        }
    }

    // ================= phase 3: deform GEMM =================
    const int warp_m = wid & 3, warp_n = wid >> 2;
    const int aRow = warp_m * 32 + lr;
    const int bRow = warp_n * 64 + lr;
    uint32_t aoff[4], boff[4];
    #pragma unroll
    for (int ks = 0; ks < 4; ++ks) {
        aoff[ks] = aRow * 128 + (((2 * ks + gk) ^ (aRow & 7)) << 4);
        boff[ks] = bRow * 128 + (((2 * ks + gk) ^ (bRow & 7)) << 4);
    }

    float acc[64];
    #pragma unroll
    for (int i = 0; i < 64; ++i) acc[i] = 0.f;

    const float* xtb = g_xt + (size_t)b * HW * CIN;

    for (int ch = 0; ch < 9; ++ch) {
        __syncthreads();
        // stage A hi+lo via cp.async (16KB each)
        #pragma unroll
        for (int j = 0; j < 4; ++j) {
            int i = tid + j * 256;
            cpasync16(smem_base + SM_AHI + i * 16, (const char*)(g_whi + ch * 8192) + i * 16, 16);
            cpasync16(smem_base + SM_ALO + i * 16, (const char*)(g_wlo + ch * 8192) + i * 16, 16);
        }
        // im2col for tap ch (fp16 output, hi only)
        #pragma unroll
        for (int it = 0; it < 8; ++it) {
            int i = tid + it * 256;
            int pxl = i >> 4, c0 = (i & 15) * 4;
            int ti = pxl * 9 + ch;
            float4 w = ((const float4*)(smemc + SM_TAPW))[ti];
            int offA = ((const int*)(smemc + SM_TAPO))[ti];
            const float* pb = xtb + offA + c0;
            float4 p00 = *(const float4*)(pb);
            float4 p01 = *(const float4*)(pb + CIN);
            float4 p10 = *(const float4*)(pb + Ww * CIN);
            float4 p11 = *(const float4*)(pb + Ww * CIN + CIN);
            float v0 = w.x * (w.z * p00.x + w.w * p01.x) + w.y * (w.z * p10.x + w.w * p11.x);
            float v1 = w.x * (w.z * p00.y + w.w * p01.y) + w.y * (w.z * p10.y + w.w * p11.y);
            float v2 = w.x * (w.z * p00.z + w.w * p01.z) + w.y * (w.z * p10.z + w.w * p11.z);
            float v3 = w.x * (w.z * p00.w + w.w * p01.w) + w.y * (w.z * p10.w + w.w * p11.w);
            __half2 h01 = __floats2half2_rn(v0, v1);
            __half2 h23 = __floats2half2_rn(v2, v3);
            uint2 hv;
            hv.x = *(uint32_t*)&h01;
            hv.y = *(uint32_t*)&h23;
            int sw = swz(pxl * 128 + c0 * 2);
            *(uint2*)(smemc + SM_B + sw) = hv;
        }
        cpasync_wait_all();
        __syncthreads();

        const uint32_t Ahi = smem_base + SM_AHI, Alo = smem_base + SM_ALO;
        const uint32_t Bp  = smem_base + SM_B;
        #pragma unroll
        for (int ks = 0; ks < 4; ++ks) {
            uint32_t ah[2][4], al[2][4];
            ldsm4(ah[0], Ahi + aoff[ks]);
            ldsm4(ah[1], Ahi + aoff[ks] + 2048);
            ldsm4(al[0], Alo + aoff[ks]);
            ldsm4(al[1], Alo + aoff[ks] + 2048);
            #pragma unroll
            for (int nt = 0; nt < 4; ++nt) {
                uint32_t bh[4];
                ldsm4(bh, Bp + boff[ks] + nt * 2048);
                #pragma unroll
                for (int mt = 0; mt < 2; ++mt) {
                    float* d0 = acc + (mt * 8 + nt * 2) * 4;
                    float* d1 = d0 + 4;
                    mma_fp16(d0, ah[mt], bh[0], bh[2]);
                    mma_fp16(d1, ah[mt], bh[1], bh[3]);
                    mma_fp16(d0, al[mt], bh[0], bh[2]);
                    mma_fp16(d1, al[mt], bh[1], bh[3]);
                }
            }
        }
    }

    const int row  = lane >> 2, colp = (lane & 3) * 2;
    float* outb = out + (size_t)b * CO * HW + base;
    #pragma unroll
    for (int mt = 0; mt < 2; ++mt) {
        int o0 = warp_m * 32 + mt * 16 + row;
        float b0 = bias[o0], b1 = bias[o0 + 8];
        #pragma unroll
        for (int n8 = 0; n8 < 8; ++n8) {
            const float* d = acc + (mt * 8 + n8) * 4;
            int pxo = warp_n * 64 + n8 * 8 + colp;
            *(float2*)(outb + (size_t)o0 * HW + pxo)       = make_float2(d[0] + b0, d[1] + b0);
            *(float2*)(outb + (size_t)(o0 + 8) * HW + pxo) = make_float2(d[2] + b1, d[3] + b1);
        }
    }
}

// ---------------------------------------------------------------------------
extern "C" void kernel_launch(void* const* d_in, const int* in_sizes, int n_in,
                              void* d_out, int out_size)
{
    const float* x   = (const float*)d_in[0];   // [8,64,96,96]
    const float* ow  = (const float*)d_in[1];   // [18,64,3,3]
    const float* ob  = (const float*)d_in[2];   // [18]
    const float* mw  = (const float*)d_in[3];   // [9,64,3,3]
    const float* mb  = (const float*)d_in[4];   // [9]
    const float* wgt = (const float*)d_in[5];   // [128,64,3,3]
    const float* bs  = (const float*)d_in[6];   // [128]
    float* out = (float*)d_out;                 // [8,128,96,96]

    cudaFuncSetAttribute(k_main, cudaFuncAttributeMaxDynamicSharedMemorySize, SM_TOTAL);

    k_wprep  <<<288, 256>>>(wgt);
    k_wprep2 <<<72, 256>>>(ow, mw);
    k_xt     <<<dim3(288, 2, 8), 256>>>(x);
    k_main   <<<dim3(72, 8), 256, SM_TOTAL>>>(ob, mb, bs, out);
}

// round 13
// speedup vs baseline: 1.5035x; 1.0272x over previous
#include <cuda_runtime.h>
#include <cuda_fp16.h>
#include <math.h>
#include <stdint.h>

static constexpr int Hh  = 96;
static constexpr int Ww  = 96;
static constexpr int HW  = 96 * 96;      // 9216
static constexpr int CIN = 64;
static constexpr int CO  = 128;
static constexpr int NB  = 8;

// Scratch (no cudaMalloc allowed).
__device__ float  g_xt [NB * HW * CIN];         // x transposed: [b][hw][c] fp32
__device__ __half g_xth[NB * HW * CIN];         // fp16 of x_t
__device__ __half g_whi [9 * 8192];             // main weights per-tap swizzled fp16 hi
__device__ __half g_wlo [9 * 8192];             //                               fp16 lo
__device__ __half g_owhi[9 * 2048];             // off/mask weights [32 pad][64] hi
__device__ __half g_owlo[9 * 2048];             //                               lo

__device__ __forceinline__ int swz(int off) { return off ^ ((off >> 3) & 0x70); }
__device__ __forceinline__ uint32_t smem_u32(const void* p) {
    uint32_t a;
    asm("{ .reg .u64 t; cvta.to.shared.u64 t, %1; cvt.u32.u64 %0, t; }" : "=r"(a) : "l"(p));
    return a;
}
__device__ __forceinline__ void ldsm4(uint32_t* r, uint32_t a) {
    asm volatile("ldmatrix.sync.aligned.m8n8.x4.shared.b16 {%0,%1,%2,%3}, [%4];"
        : "=r"(r[0]), "=r"(r[1]), "=r"(r[2]), "=r"(r[3]) : "r"(a));
}
__device__ __forceinline__ void mma_fp16(float* d, const uint32_t* a,
                                         uint32_t b0, uint32_t b1) {
    asm volatile("mma.sync.aligned.m16n8k16.row.col.f32.f16.f16.f32 "
        "{%0,%1,%2,%3}, {%4,%5,%6,%7}, {%8,%9}, {%0,%1,%2,%3};"
        : "+f"(d[0]), "+f"(d[1]), "+f"(d[2]), "+f"(d[3])
        : "r"(a[0]), "r"(a[1]), "r"(a[2]), "r"(a[3]), "r"(b0), "r"(b1));
}
__device__ __forceinline__ void cpasync16(uint32_t dst, const void* src, int srcBytes) {
    asm volatile("cp.async.cg.shared.global [%0], [%1], 16, %2;"
        :: "r"(dst), "l"(src), "r"(srcBytes) : "memory");
}
__device__ __forceinline__ void cpasync_wait_all() {
    asm volatile("cp.async.wait_all;" ::: "memory");
}
__device__ __forceinline__ void cpasync_commit() {
    asm volatile("cp.async.commit_group;" ::: "memory");
}
__device__ __forceinline__ void cpasync_wait1() {
    asm volatile("cp.async.wait_group 1;" ::: "memory");
}
__device__ __forceinline__ void cpasync_wait0() {
    asm volatile("cp.async.wait_group 0;" ::: "memory");
}

// ---------------------------------------------------------------------------
// Kernel W: split main-conv weights into fp16 hi/lo (tap-major k, SW128).
// ---------------------------------------------------------------------------
__global__ void k_wprep(const float* __restrict__ wgt) {
    int i = blockIdx.x * 256 + threadIdx.x;      // 128*576
    if (i >= 128 * 576) return;
    int o = i / 576, r = i % 576;
    int t = r / 64, c = r % 64;
    float v = wgt[o * 576 + c * 9 + t];
    __half h = __float2half_rn(v);
    float lo = v - __half2float(h);
    int sw = swz(o * 128 + c * 2) >> 1;
    g_whi[t * 8192 + sw] = h;
    g_wlo[t * 8192 + sw] = __float2half_rn(lo);
}

// ---------------------------------------------------------------------------
// Kernel W2: split offset+mask weights [32 pad o][64 c] per tap, fp16 hi/lo.
// ---------------------------------------------------------------------------
__global__ void k_wprep2(const float* __restrict__ ow, const float* __restrict__ mw) {
    int i = blockIdx.x * 256 + threadIdx.x;      // 9*32*64 = 18432
    if (i >= 18432) return;
    int t = i / 2048, r = i % 2048;
    int o = r / 64, c = r % 64;
    float v = 0.f;
    if (o < 18)      v = ow[o * 576 + c * 9 + t];
    else if (o < 27) v = mw[(o - 18) * 576 + c * 9 + t];
    __half h = __float2half_rn(v);
    float lo = v - __half2float(h);
    int sw = swz(o * 128 + c * 2) >> 1;
    g_owhi[t * 2048 + sw] = h;
    g_owlo[t * 2048 + sw] = __float2half_rn(lo);
}

// ---------------------------------------------------------------------------
// Kernel X: transpose x[b][c][hw] -> g_xt[b][hw][c] (fp32) + fp16.
// ---------------------------------------------------------------------------
__global__ __launch_bounds__(256) void k_xt(const float* __restrict__ x) {
    __shared__ float t[32][33];
    const int b = blockIdx.z, c0 = blockIdx.y * 32, hw0 = blockIdx.x * 32;
    const int lx = threadIdx.x & 31, ly = threadIdx.x >> 5;
    const float* xb = x + (size_t)b * CIN * HW;
    #pragma unroll
    for (int j = ly; j < 32; j += 8)
        t[j][lx] = xb[(c0 + j) * HW + hw0 + lx];
    __syncthreads();
    float* xt  = g_xt  + (size_t)b * HW * CIN;
    __half* xh = g_xth + (size_t)b * HW * CIN;
    #pragma unroll
    for (int j = ly; j < 32; j += 8) {
        float v = t[lx][j];
        size_t idx = (size_t)(hw0 + j) * CIN + c0 + lx;
        xt[idx] = v;
        xh[idx] = __float2half_rn(v);
    }
}

// ---------------------------------------------------------------------------
// Fused kernel. Phase 1 is now a cp.async double-buffered pipeline (its
// staging is pure cp.async, so overlap is free). Phase 3 as R12.
// smem: slot0 0..24576 (A_hi 4K | A_lo 4K | B 16K), slot1 24576..49152.
// Phase 3 reuses 0..49152 as A_hi 16K | A_lo 16K | B 16K.
// tapW 49152 (18432) | tapO 67584 (4608) | om 72192 (13824) | total 86016.
// ---------------------------------------------------------------------------
static constexpr int SM_SLOT = 24576;   // phase-1 slot stride
static constexpr int SM_AHI  = 0;       // phase-3 layout
static constexpr int SM_ALO  = 16384;
static constexpr int SM_B    = 32768;
static constexpr int SM_TAPW = 49152;
static constexpr int SM_TAPO = 67584;
static constexpr int SM_OM   = 72192;
static constexpr int SM_TOTAL = 86016;

__global__ __launch_bounds__(256, 2) void k_main(
    const float* __restrict__ ob, const float* __restrict__ mb,
    const float* __restrict__ bias, float* __restrict__ out)
{
    extern __shared__ __align__(128) char smemc[];
    const uint32_t smem_base = smem_u32(smemc);
    const int tid  = threadIdx.x;
    const int wid  = tid >> 5, lane = tid & 31;
    const int b    = blockIdx.y;
    const int base = blockIdx.x * 128;

    const __half* xhp = g_xth + (size_t)b * HW * CIN;
    const int lr = lane & 15, gk = lane >> 4;

    // ================= phase 1: offset+mask conv (cp.async pipeline) ========
    {
        uint32_t aoffm[2][4], boff[4];
        #pragma unroll
        for (int mt = 0; mt < 2; ++mt) {
            int aRow = mt * 16 + lr;
            #pragma unroll
            for (int ks = 0; ks < 4; ++ks)
                aoffm[mt][ks] = aRow * 128 + (((2 * ks + gk) ^ (aRow & 7)) << 4);
        }
        {
            int bRow = wid * 16 + lr;
            #pragma unroll
            for (int ks = 0; ks < 4; ++ks)
                boff[ks] = bRow * 128 + (((2 * ks + gk) ^ (bRow & 7)) << 4);
        }

        float acc[2][2][4];
        #pragma unroll
        for (int mt = 0; mt < 2; ++mt)
            #pragma unroll
            for (int nt = 0; nt < 2; ++nt)
                #pragma unroll
                for (int j = 0; j < 4; ++j) acc[mt][nt][j] = 0.f;

        // stage chunk ch (A hi+lo 8K + B 16K) into slot base sb
        auto stage1 = [&](int ch, uint32_t sb) {
            cpasync16(sb + tid * 16,        (const char*)(g_owhi + ch * 2048) + tid * 16, 16);
            cpasync16(sb + 4096 + tid * 16, (const char*)(g_owlo + ch * 2048) + tid * 16, 16);
            const int dy = ch / 3 - 1, dx = ch % 3 - 1;
            #pragma unroll
            for (int it = 0; it < 4; ++it) {
                int i = tid + it * 256;         // 1024 items: 128px x 8 chunks
                int pxl = i >> 3, ci = i & 7;
                int p = base + pxl;
                int ho = p / Ww, wo = p - ho * Ww;
                int sy = ho + dy, sx = wo + dx;
                bool valid = (unsigned)sy < (unsigned)Hh && (unsigned)sx < (unsigned)Ww;
                int syc = min(max(sy, 0), Hh - 1), sxc = min(max(sx, 0), Ww - 1);
                size_t q = (size_t)(syc * Ww + sxc) * CIN + ci * 8;
                int sw = swz(pxl * 128 + ci * 16);
                cpasync16(sb + 8192 + sw, xhp + q, valid ? 16 : 0);
            }
        };

        stage1(0, smem_base);           cpasync_commit();
        stage1(1, smem_base + SM_SLOT); cpasync_commit();
        cpasync_wait1();                // chunk 0 landed
        __syncthreads();

        for (int ch = 0; ch < 9; ++ch) {
            const uint32_t sb = smem_base + (ch & 1) * SM_SLOT;
            const uint32_t Ahi = sb, Alo = sb + 4096, Bp = sb + 8192;
            #pragma unroll
            for (int ks = 0; ks < 4; ++ks) {
                uint32_t ah[2][4], al[2][4], bh[4];
                ldsm4(ah[0], Ahi + aoffm[0][ks]);
                ldsm4(ah[1], Ahi + aoffm[1][ks]);
                ldsm4(al[0], Alo + aoffm[0][ks]);
                ldsm4(al[1], Alo + aoffm[1][ks]);
                ldsm4(bh, Bp + boff[ks]);
                #pragma unroll
                for (int mt = 0; mt < 2; ++mt) {
                    float* d0 = acc[mt][0];
                    float* d1 = acc[mt][1];
                    mma_fp16(d0, ah[mt], bh[0], bh[2]);
                    mma_fp16(d1, ah[mt], bh[1], bh[3]);
                    mma_fp16(d0, al[mt], bh[0], bh[2]);
                    mma_fp16(d1, al[mt], bh[1], bh[3]);
                }
            }
            __syncthreads();            // all warps done reading slot (ch&1)
            if (ch + 2 < 9) {
                stage1(ch + 2, sb);     // refill just-consumed slot
                cpasync_commit();
                cpasync_wait1();        // chunk ch+1 landed (issued >=1 interval ago)
            } else {
                cpasync_wait0();        // drain: chunk ch+1 landed
            }
            __syncthreads();
        }

        // epilogue -> smem om[27][128]
        float* om = (float*)(smemc + SM_OM);
        const int row = lane >> 2, colp = (lane & 3) * 2;
        #pragma unroll
        for (int mt = 0; mt < 2; ++mt) {
            #pragma unroll
            for (int nt = 0; nt < 2; ++nt) {
                const float* d = acc[mt][nt];
                int p = wid * 16 + nt * 8 + colp;
                #pragma unroll
                for (int half = 0; half < 2; ++half) {
                    int o = mt * 16 + half * 8 + row;
                    float v0 = d[half * 2], v1 = d[half * 2 + 1];
                    if (o < 18) {
                        float bo = ob[o];
                        *(float2*)(om + o * 128 + p) = make_float2(v0 + bo, v1 + bo);
                    } else if (o < 27) {
                        float bo = mb[o - 18];
                        float s0 = 1.f / (1.f + __expf(-(v0 + bo)));
                        float s1 = 1.f / (1.f + __expf(-(v1 + bo)));
                        *(float2*)(om + o * 128 + p) = make_float2(s0, s1);
                    }
                }
            }
        }
    }
    __syncthreads();

    // ================= phase 2: tap table =================
    {
        const float* om = (const float*)(smemc + SM_OM);
        for (int i = tid; i < 128 * 9; i += 256) {
            int pxl = i / 9, t = i % 9;
            int p = base + pxl;
            int ho = p / Ww, wo = p - ho * Ww;
            float dy = om[(2 * t) * 128 + pxl];
            float dx = om[(2 * t + 1) * 128 + pxl];
            float m  = om[(18 + t) * 128 + pxl];
            float fy = (float)(ho - 1 + t / 3) + dy;
            float fx = (float)(wo - 1 + t % 3) + dx;
            float y0f = floorf(fy), x0f = floorf(fx);
            int y0 = (int)y0f, x0 = (int)x0f;
            float ly = fy - y0f, lx = fx - x0f;
            float hy = 1.f - ly, hx = 1.f - lx;
            float rwA = 0.f, rwB = 0.f, cwA = 0.f, cwB = 0.f;
            if (y0 >= 0 && y0 <= Hh - 2)      { rwA = hy; rwB = ly; }
            else if (y0 == -1)                { rwA = ly; }
            else if (y0 == Hh - 1)            { rwB = hy; }
            if (x0 >= 0 && x0 <= Ww - 2)      { cwA = hx; cwB = lx; }
            else if (x0 == -1)                { cwA = lx; }
            else if (x0 == Ww - 1)            { cwB = hx; }
            rwA *= m; rwB *= m;
            int by = min(max(y0, 0), Hh - 2);
            int bx = min(max(x0, 0), Ww - 2);
            ((float4*)(smemc + SM_TAPW))[i] = make_float4(rwA, rwB, cwA, cwB);
            ((int*)(smemc + SM_TAPO))[i] = (by * Ww + bx) * CIN;
        }
    }

    // ================= phase 3: deform GEMM =================
    const int warp_m = wid & 3, warp_n = wid >> 2;
    const int aRow = warp_m * 32 + lr;
    const int bRow = warp_n * 64 + lr;
    uint32_t aoff[4], boff[4];
    #pragma unroll
    for (int ks = 0; ks < 4; ++ks) {
        aoff[ks] = aRow * 128 + (((2 * ks + gk) ^ (aRow & 7)) << 4);
        boff[ks] = bRow * 128 + (((2 * ks + gk) ^ (bRow & 7)) << 4);
    }

    float acc[64];
    #pragma unroll
    for (int i = 0; i < 64; ++i) acc[i] = 0.f;

    const float* xtb = g_xt + (size_t)b * HW * CIN;

    for (int ch = 0; ch < 9; ++ch) {
        __syncthreads();
        // stage A hi+lo via cp.async (16KB each)
        #pragma unroll
        for (int j = 0; j < 4; ++j) {
            int i = tid + j * 256;
            cpasync16(smem_base + SM_AHI + i * 16, (const char*)(g_whi + ch * 8192) + i * 16, 16);
            cpasync16(smem_base + SM_ALO + i * 16, (const char*)(g_wlo + ch * 8192) + i * 16, 16);
        }
        // im2col for tap ch (fp16 output)
        #pragma unroll
        for (int it = 0; it < 8; ++it) {
            int i = tid + it * 256;
            int pxl = i >> 4, c0 = (i & 15) * 4;
            int ti = pxl * 9 + ch;
            float4 w = ((const float4*)(smemc + SM_TAPW))[ti];
            int offA = ((const int*)(smemc + SM_TAPO))[ti];
            const float* pb = xtb + offA + c0;
            float4 p00 = *(const float4*)(pb);
            float4 p01 = *(const float4*)(pb + CIN);
            float4 p10 = *(const float4*)(pb + Ww * CIN);
            float4 p11 = *(const float4*)(pb + Ww * CIN + CIN);
            float v0 = w.x * (w.z * p00.x + w.w * p01.x) + w.y * (w.z * p10.x + w.w * p11.x);
            float v1 = w.x * (w.z * p00.y + w.w * p01.y) + w.y * (w.z * p10.y + w.w * p11.y);
            float v2 = w.x * (w.z * p00.z + w.w * p01.z) + w.y * (w.z * p10.z + w.w * p11.z);
            float v3 = w.x * (w.z * p00.w + w.w * p01.w) + w.y * (w.z * p10.w + w.w * p11.w);
            __half2 h01 = __floats2half2_rn(v0, v1);
            __half2 h23 = __floats2half2_rn(v2, v3);
            uint2 hv;
            hv.x = *(uint32_t*)&h01;
            hv.y = *(uint32_t*)&h23;
            int sw = swz(pxl * 128 + c0 * 2);
            *(uint2*)(smemc + SM_B + sw) = hv;
        }
        cpasync_wait_all();
        __syncthreads();

        const uint32_t Ahi = smem_base + SM_AHI, Alo = smem_base + SM_ALO;
        const uint32_t Bp  = smem_base + SM_B;
        #pragma unroll
        for (int ks = 0; ks < 4; ++ks) {
            uint32_t ah[2][4], al[2][4];
            ldsm4(ah[0], Ahi + aoff[ks]);
            ldsm4(ah[1], Ahi + aoff[ks] + 2048);
            ldsm4(al[0], Alo + aoff[ks]);
            ldsm4(al[1], Alo + aoff[ks] + 2048);
            #pragma unroll
            for (int nt = 0; nt < 4; ++nt) {
                uint32_t bh[4];
                ldsm4(bh, Bp + boff[ks] + nt * 2048);
                #pragma unroll
                for (int mt = 0; mt < 2; ++mt) {
                    float* d0 = acc + (mt * 8 + nt * 2) * 4;
                    float* d1 = d0 + 4;
                    mma_fp16(d0, ah[mt], bh[0], bh[2]);
                    mma_fp16(d1, ah[mt], bh[1], bh[3]);
                    mma_fp16(d0, al[mt], bh[0], bh[2]);
                    mma_fp16(d1, al[mt], bh[1], bh[3]);
                }
            }
        }
    }

    const int row  = lane >> 2, colp = (lane & 3) * 2;
    float* outb = out + (size_t)b * CO * HW + base;
    #pragma unroll
    for (int mt = 0; mt < 2; ++mt) {
        int o0 = warp_m * 32 + mt * 16 + row;
        float b0 = bias[o0], b1 = bias[o0 + 8];
        #pragma unroll
        for (int n8 = 0; n8 < 8; ++n8) {
            const float* d = acc + (mt * 8 + n8) * 4;
            int pxo = warp_n * 64 + n8 * 8 + colp;
            *(float2*)(outb + (size_t)o0 * HW + pxo)       = make_float2(d[0] + b0, d[1] + b0);
            *(float2*)(outb + (size_t)(o0 + 8) * HW + pxo) = make_float2(d[2] + b1, d[3] + b1);
        }
    }
}

// ---------------------------------------------------------------------------
extern "C" void kernel_launch(void* const* d_in, const int* in_sizes, int n_in,
                              void* d_out, int out_size)
{
    const float* x   = (const float*)d_in[0];   // [8,64,96,96]
    const float* ow  = (const float*)d_in[1];   // [18,64,3,3]
    const float* ob  = (const float*)d_in[2];   // [18]
    const float* mw  = (const float*)d_in[3];   // [9,64,3,3]
    const float* mb  = (const float*)d_in[4];   // [9]
    const float* wgt = (const float*)d_in[5];   // [128,64,3,3]
    const float* bs  = (const float*)d_in[6];   // [128]
    float* out = (float*)d_out;                 // [8,128,96,96]

    cudaFuncSetAttribute(k_main, cudaFuncAttributeMaxDynamicSharedMemorySize, SM_TOTAL);

    k_wprep  <<<288, 256>>>(wgt);
    k_wprep2 <<<72, 256>>>(ow, mw);
    k_xt     <<<dim3(288, 2, 8), 256>>>(x);
    k_main   <<<dim3(72, 8), 256, SM_TOTAL>>>(ob, mb, bs, out);
}